// round 12
// baseline (speedup 1.0000x reference)
#include <cuda_runtime.h>
#include <cuda_fp16.h>
#include <cstdint>

// ============================================================================
// out[m,n] = sum_e softmax(x@Wg+bg)[m,e] * (x@We[e] + be[e])[n]
// Fused single GEMM (fp16 in / fp32 accum via mma.sync):
//   A'[m, e*1024+k] = g[m,e]*x[m,k], bias tail A'[m,8192+e]=g[m,e]
//   W'[n][e*1024+k] = We[e,k,n],     bias tail W'[n][8192+e]=be[e,n]
//   K_ext = 8256 ;  out = A' @ W'^T   (M=8192, N=1024)
// R11: CTA 128x128x64 with 128 threads / 4 warps, warp tile 64x64
// (192 B smem per HMMA vs 256 in R10), 2 independent CTAs/SM, fragment
// double-buffering. Single fused prep kernel.
// ============================================================================

#define NE 8
#define INF 1024
#define OUTF 1024
#define NTOK 8192
#define KSEG 8192
#define KTOT 8256            // 8192 + 64 (bias tail, zero padded)
#define KI 129               // KTOT / 64

// GEMM tile config
#define BM 128
#define BN 128
#define BK 64
#define THREADS 128
#define STAGES 3
#define STAGE_BYTES 32768    // (BM+BN)*BK*2
#define SB_B_OFF 16384       // A: 16KB then B: 16KB
#define SMEM_BYTES (STAGES * STAGE_BYTES)   // 96KB -> 2 CTAs/SM
#define VSTRIDE16 (16 * KTOT * 2)           // 16 rows of fp16

// fused prep kernel block ranges
#define PREP_GATE_BLOCKS  (NTOK / 8)            // 1024
#define PREP_W_BLOCKS     (NE * 32 * 32)        // 8192
#define PREP_TAILW_BLOCKS ((OUTF * 64) / 256)   // 256
#define PREP_BLOCKS (PREP_GATE_BLOCKS + PREP_W_BLOCKS + PREP_TAILW_BLOCKS)

// ---- scratch (device globals; no allocation allowed) ----
__device__ __align__(16) __half g_A[(size_t)NTOK * KTOT];   // ~135 MB
__device__ __align__(16) __half g_W[(size_t)OUTF * KTOT];   // ~17 MB

// ============================================================================
// PTX helpers — baseline (sm_80-class) only
// ============================================================================
__device__ __forceinline__ uint32_t smem_u32(const void* p) {
    uint32_t a;
    asm("{ .reg .u64 t; cvta.to.shared.u64 t, %1; cvt.u32.u64 %0, t; }"
        : "=r"(a) : "l"(p));
    return a;
}

#define CP_ASYNC16(saddr, gaddr) \
    asm volatile("cp.async.cg.shared.global [%0], [%1], 16;" \
                 :: "r"(saddr), "l"(gaddr))

#define CP_COMMIT() asm volatile("cp.async.commit_group;" ::: "memory")
#define CP_WAIT1()  asm volatile("cp.async.wait_group 1;" ::: "memory")
#define CP_WAIT0()  asm volatile("cp.async.wait_group 0;" ::: "memory")

#define LDSM_X4(r0, r1, r2, r3, addr) \
    asm volatile("ldmatrix.sync.aligned.m8n8.x4.shared.b16 {%0,%1,%2,%3}, [%4];" \
                 : "=r"(r0), "=r"(r1), "=r"(r2), "=r"(r3) : "r"(addr))

#define MMA_16816(c, a, b0v, b1v) \
    asm volatile("mma.sync.aligned.m16n8k16.row.col.f32.f16.f16.f32 " \
                 "{%0,%1,%2,%3}, {%4,%5,%6,%7}, {%8,%9}, {%0,%1,%2,%3};" \
                 : "+f"((c)[0]), "+f"((c)[1]), "+f"((c)[2]), "+f"((c)[3]) \
                 : "r"((a)[0]), "r"((a)[1]), "r"((a)[2]), "r"((a)[3]), \
                   "r"(b0v), "r"(b1v))

// ============================================================================
// Fused prep kernel — one launch, three block families:
//   [0, 1024)        : gate softmax + A' write (+ bias tail of A)
//   [1024, 9216)     : W transpose/convert
//   [9216, 9472)     : W bias tail
// ============================================================================
__global__ __launch_bounds__(256) void prep_kernel(
    const float* __restrict__ x, const float* __restrict__ Wg,
    const float* __restrict__ bg, const float* __restrict__ We,
    const float* __restrict__ be) {
    __shared__ float wgs[INF * NE];   // 32KB (gate branch)
    __shared__ float gs[8][NE];
    __shared__ float tile[32][33];    // transpose branch

    int tid = threadIdx.x;
    int blk = blockIdx.x;

    if (blk < PREP_GATE_BLOCKS) {
        // ---- gate softmax + A' ----
        for (int i = tid; i < INF * NE / 4; i += 256)
            ((float4*)wgs)[i] = ((const float4*)Wg)[i];
        __syncthreads();

        int w = tid >> 5, lane = tid & 31;
        int t = blk * 8 + w;
        const float* xr = x + (size_t)t * INF;

        float acc[NE];
#pragma unroll
        for (int e = 0; e < NE; e++) acc[e] = 0.f;
        for (int i = lane; i < INF; i += 32) {
            float xv = xr[i];
            float4 a = ((const float4*)wgs)[i * 2];
            float4 b = ((const float4*)wgs)[i * 2 + 1];
            acc[0] += xv * a.x; acc[1] += xv * a.y;
            acc[2] += xv * a.z; acc[3] += xv * a.w;
            acc[4] += xv * b.x; acc[5] += xv * b.y;
            acc[6] += xv * b.z; acc[7] += xv * b.w;
        }
#pragma unroll
        for (int e = 0; e < NE; e++)
#pragma unroll
            for (int off = 16; off; off >>= 1)
                acc[e] += __shfl_xor_sync(0xffffffffu, acc[e], off);

        if (lane == 0) {
            float mx = -1e30f;
#pragma unroll
            for (int e = 0; e < NE; e++) { acc[e] += bg[e]; mx = fmaxf(mx, acc[e]); }
            float s = 0.f;
#pragma unroll
            for (int e = 0; e < NE; e++) { acc[e] = expf(acc[e] - mx); s += acc[e]; }
            float inv = 1.0f / s;
#pragma unroll
            for (int e = 0; e < NE; e++) gs[w][e] = acc[e] * inv;
        }
        __syncthreads();

#pragma unroll 1
        for (int tok = 0; tok < 8; tok++) {
            int m = blk * 8 + tok;
            const float* xs = x + (size_t)m * INF;
            __half* arow = g_A + (size_t)m * KTOT;
            for (int u = tid; u < 1024; u += 256) {
                int e  = u >> 7;
                int k8 = (u & 127) << 3;
                float g = gs[tok][e];
                float4 a = ((const float4*)(xs + k8))[0];
                float4 b = ((const float4*)(xs + k8))[1];
                float v[8] = {a.x, a.y, a.z, a.w, b.x, b.y, b.z, b.w};
                __align__(16) __half h[8];
#pragma unroll
                for (int i = 0; i < 8; i++) h[i] = __float2half_rn(g * v[i]);
                *(uint4*)(arow + e * INF + k8) = *(const uint4*)h;
            }
            for (int j = tid; j < 64; j += 256)
                arow[KSEG + j] = (j < NE) ? __float2half_rn(gs[tok][j])
                                          : __half(0.f);
        }
    } else if (blk < PREP_GATE_BLOCKS + PREP_W_BLOCKS) {
        // ---- W transpose/convert ----
        int b  = blk - PREP_GATE_BLOCKS;
        int e  = b >> 10;
        int kt = (b >> 5) & 31;
        int nt = b & 31;

        int tx = tid & 31, ty = tid >> 5;
        const float* base = We + (size_t)e * INF * OUTF;

#pragma unroll
        for (int i = 0; i < 4; i++) {
            int k = kt * 32 + ty + i * 8;
            tile[ty + i * 8][tx] = base[(size_t)k * OUTF + nt * 32 + tx];
        }
        __syncthreads();
#pragma unroll
        for (int i = 0; i < 4; i++) {
            int nrow = nt * 32 + ty + i * 8;
            float v = tile[tx][ty + i * 8];
            g_W[(size_t)nrow * KTOT + e * INF + kt * 32 + tx] = __float2half_rn(v);
        }
    } else {
        // ---- W bias tail ----
        int idx = (blk - PREP_GATE_BLOCKS - PREP_W_BLOCKS) * 256 + tid;
        int n = idx >> 6;
        int j = idx & 63;
        g_W[(size_t)n * KTOT + KSEG + j] =
            (j < NE) ? __float2half_rn(be[(size_t)j * OUTF + n]) : __half(0.f);
    }
}

// ============================================================================
// Main GEMM: out[8192,1024] = A'[M,KTOT] @ W'[N,KTOT]^T   fp16->fp32
// CTA 128x128x64, 128 thr (4 warps 2m x 2n, warp tile 64x64), 3-stage
// cp.async, 2 CTAs/SM, fragment double-buffering.
// ============================================================================
__device__ __forceinline__ void issue_stage(uint32_t stb, const char* gA,
                                            const char* gB, uint32_t sAo,
                                            int kbyte) {
#pragma unroll
    for (int v = 0; v < 8; v++)
        CP_ASYNC16(stb + sAo + v * 2048, gA + kbyte + (size_t)v * VSTRIDE16);
#pragma unroll
    for (int v = 0; v < 8; v++)
        CP_ASYNC16(stb + SB_B_OFF + sAo + v * 2048,
                   gB + kbyte + (size_t)v * VSTRIDE16);
    CP_COMMIT();
}

__global__ __launch_bounds__(THREADS, 2) void moe_gemm_kernel(float* __restrict__ out) {
    extern __shared__ __align__(128) char smem[];
    uint32_t sb = smem_u32(smem);

    int tid  = threadIdx.x;
    int lane = tid & 31;
    int wid  = tid >> 5;
    int wm   = wid & 1;          // 2 warp-rows  (m)  64 rows each
    int wn   = wid >> 1;         // 2 warp-cols  (n)  64 cols each
    int m0   = blockIdx.y * BM;
    int n0   = blockIdx.x * BN;

    // ---- cp.async per-thread invariants (128 thr: 16 rows x 8 chunks) ----
    int rA = tid >> 3;           // 0..15
    int ch = tid & 7;
    const char* gA = (const char*)(g_A + (size_t)(m0 + rA) * KTOT + ch * 8);
    const char* gB = (const char*)(g_W + (size_t)(n0 + rA) * KTOT + ch * 8);
    // (rA+16v)&7 == rA&7 -> one swizzled offset serves all row groups
    uint32_t sAo = (uint32_t)(rA * 128 + ((ch ^ (rA & 7)) << 4));

    // ---- ldmatrix per-thread invariants ----
    int aRow0 = wm * 64 + (lane & 15);
    int ah    = lane >> 4;
    int ax7   = aRow0 & 7;
    int bRow0 = wn * 64 + (lane & 7) + ((lane >> 4) << 3);
    int bh    = (lane >> 3) & 1;
    int bx7   = bRow0 & 7;

    uint32_t aBase[4], bBase[4];
#pragma unroll
    for (int mt = 0; mt < 4; mt++) aBase[mt] = (uint32_t)((aRow0 + mt * 16) * 128);
#pragma unroll
    for (int np = 0; np < 4; np++)
        bBase[np] = (uint32_t)(SB_B_OFF + (bRow0 + np * 16) * 128);

    float acc[4][8][4];
#pragma unroll
    for (int mt = 0; mt < 4; mt++)
#pragma unroll
        for (int nt = 0; nt < 8; nt++)
#pragma unroll
            for (int q = 0; q < 4; q++) acc[mt][nt][q] = 0.f;

    // ---- prologue: stages 0,1 ----
    issue_stage(sb + 0 * STAGE_BYTES, gA, gB, sAo, 0 * 128);
    issue_stage(sb + 1 * STAGE_BYTES, gA, gB, sAo, 1 * 128);

    uint32_t af[2][4][4], bf[2][4][4];

    // ---- main loop ----
    int buf = 0;                      // stage i lives in buffer (i % 3)
    for (int i = 0; i < KI; i++) {
        if (i < KI - 1) CP_WAIT1(); else CP_WAIT0();
        __syncthreads();

        if (i + 2 < KI) {
            int nb = buf + 2; if (nb >= STAGES) nb -= STAGES;
            issue_stage(sb + nb * STAGE_BYTES, gA, gB, sAo, (i + 2) * 128);
        }

        uint32_t stb = sb + buf * STAGE_BYTES;
        if (++buf == STAGES) buf = 0;

        // preload slice 0 fragments
        {
            uint32_t cpA = (uint32_t)((ah ^ ax7) << 4);
            uint32_t cpB = (uint32_t)((bh ^ bx7) << 4);
#pragma unroll
            for (int mt = 0; mt < 4; mt++)
                LDSM_X4(af[0][mt][0], af[0][mt][1], af[0][mt][2], af[0][mt][3],
                        stb + aBase[mt] + cpA);
#pragma unroll
            for (int np = 0; np < 4; np++)
                LDSM_X4(bf[0][np][0], bf[0][np][1], bf[0][np][2], bf[0][np][3],
                        stb + bBase[np] + cpB);
        }

#pragma unroll
        for (int s = 0; s < 4; s++) {
            int cur = s & 1, nxt = cur ^ 1;
            if (s < 3) {
                uint32_t cpA = (uint32_t)(((2 * (s + 1) + ah) ^ ax7) << 4);
                uint32_t cpB = (uint32_t)(((2 * (s + 1) + bh) ^ bx7) << 4);
#pragma unroll
                for (int mt = 0; mt < 4; mt++)
                    LDSM_X4(af[nxt][mt][0], af[nxt][mt][1],
                            af[nxt][mt][2], af[nxt][mt][3],
                            stb + aBase[mt] + cpA);
#pragma unroll
                for (int np = 0; np < 4; np++)
                    LDSM_X4(bf[nxt][np][0], bf[nxt][np][1],
                            bf[nxt][np][2], bf[nxt][np][3],
                            stb + bBase[np] + cpB);
            }
#pragma unroll
            for (int mt = 0; mt < 4; mt++)
#pragma unroll
                for (int np = 0; np < 4; np++) {
                    MMA_16816(acc[mt][2 * np + 0], af[cur][mt],
                              bf[cur][np][0], bf[cur][np][1]);
                    MMA_16816(acc[mt][2 * np + 1], af[cur][mt],
                              bf[cur][np][2], bf[cur][np][3]);
                }
        }
    }

    // ---- epilogue: direct 32B-sector stores (bias folded into K tail) ----
    int grp = lane >> 2;
    int tig = lane & 3;
#pragma unroll
    for (int mt = 0; mt < 4; mt++) {
        int mrow = m0 + wm * 64 + mt * 16 + grp;
#pragma unroll
        for (int nt = 0; nt < 8; nt++) {
            int ncol = n0 + wn * 64 + nt * 8 + tig * 2;
            float2 v0 = make_float2(acc[mt][nt][0], acc[mt][nt][1]);
            float2 v1 = make_float2(acc[mt][nt][2], acc[mt][nt][3]);
            *(float2*)(out + (size_t)mrow * OUTF + ncol)       = v0;
            *(float2*)(out + (size_t)(mrow + 8) * OUTF + ncol) = v1;
        }
    }
}

// ============================================================================
// Launch
// ============================================================================
extern "C" void kernel_launch(void* const* d_in, const int* in_sizes, int n_in,
                              void* d_out, int out_size) {
    (void)in_sizes; (void)n_in; (void)out_size;
    const float* x  = (const float*)d_in[0];   // [8192, 1024]
    const float* We = (const float*)d_in[1];   // [8, 1024, 1024]
    const float* be = (const float*)d_in[2];   // [8, 1024]
    const float* Wg = (const float*)d_in[3];   // [1024, 8]
    const float* bg = (const float*)d_in[4];   // [8]
    float* out = (float*)d_out;                // [8192, 1024]

    cudaFuncSetAttribute(moe_gemm_kernel,
                         cudaFuncAttributeMaxDynamicSharedMemorySize, SMEM_BYTES);

    prep_kernel<<<PREP_BLOCKS, 256>>>(x, Wg, bg, We, be);
    moe_gemm_kernel<<<dim3(OUTF / BN, NTOK / BM), THREADS, SMEM_BYTES>>>(out);
}

// round 13
// speedup vs baseline: 1.6054x; 1.6054x over previous
#include <cuda_runtime.h>
#include <cuda_fp16.h>
#include <cstdint>

// ============================================================================
// out[m,n] = sum_e softmax(x@Wg+bg)[m,e] * (x@We[e] + be[e])[n]
// Fused single GEMM (fp16 in / fp32 accum via mma.sync):
//   A'[m, e*1024+k] = g[m,e]*x[m,k], bias tail A'[m,8192+e]=g[m,e]
//   W'[n][e*1024+k] = We[e,k,n],     bias tail W'[n][8192+e]=be[e,n]
//   K_ext = 8256 ;  out = A' @ W'^T   (M=8192, N=1024)
// R12: R10 GEMM config (128x128x64, 256 thr, warp 64x32, 3 stages,
// 2 CTAs/SM) + split-K=2 to cut wave-quantization tail (352 -> 288
// iter-units makespan), separate partial buffer + reduce pass (no atomics).
// ============================================================================

#define NE 8
#define INF 1024
#define OUTF 1024
#define NTOK 8192
#define KSEG 8192
#define KTOT 8256            // 8192 + 64 (bias tail, zero padded)
#define KI 129               // KTOT / 64
#define KSPLIT0 65           // split 0: k-iters [0, 65)
#define KSPLIT1 64           // split 1: k-iters [65, 129)  (includes bias tail)

// GEMM tile config (R10, proven 351 us)
#define BM 128
#define BN 128
#define BK 64
#define THREADS 256
#define STAGES 3
#define STAGE_BYTES 32768    // (BM+BN)*BK*2
#define SB_B_OFF 16384       // A: 16KB then B: 16KB
#define SMEM_BYTES (STAGES * STAGE_BYTES)   // 96KB -> 2 CTAs/SM
#define VSTRIDE32 (32 * KTOT * 2)           // 32 rows of fp16

// ---- scratch (device globals; no allocation allowed) ----
__device__ __align__(16) __half g_A[(size_t)NTOK * KTOT];   // ~135 MB
__device__ __align__(16) __half g_W[(size_t)OUTF * KTOT];   // ~17 MB
__device__ __align__(16) float  g_P[(size_t)NTOK * OUTF];   // 32 MB split-1 partial

// ============================================================================
// PTX helpers — baseline (sm_80-class) only
// ============================================================================
__device__ __forceinline__ uint32_t smem_u32(const void* p) {
    uint32_t a;
    asm("{ .reg .u64 t; cvta.to.shared.u64 t, %1; cvt.u32.u64 %0, t; }"
        : "=r"(a) : "l"(p));
    return a;
}

#define CP_ASYNC16(saddr, gaddr) \
    asm volatile("cp.async.cg.shared.global [%0], [%1], 16;" \
                 :: "r"(saddr), "l"(gaddr))

#define CP_COMMIT() asm volatile("cp.async.commit_group;" ::: "memory")
#define CP_WAIT1()  asm volatile("cp.async.wait_group 1;" ::: "memory")
#define CP_WAIT0()  asm volatile("cp.async.wait_group 0;" ::: "memory")

#define LDSM_X4(r0, r1, r2, r3, addr) \
    asm volatile("ldmatrix.sync.aligned.m8n8.x4.shared.b16 {%0,%1,%2,%3}, [%4];" \
                 : "=r"(r0), "=r"(r1), "=r"(r2), "=r"(r3) : "r"(addr))

#define MMA_16816(c, a, b0v, b1v) \
    asm volatile("mma.sync.aligned.m16n8k16.row.col.f32.f16.f16.f32 " \
                 "{%0,%1,%2,%3}, {%4,%5,%6,%7}, {%8,%9}, {%0,%1,%2,%3};" \
                 : "+f"((c)[0]), "+f"((c)[1]), "+f"((c)[2]), "+f"((c)[3]) \
                 : "r"((a)[0]), "r"((a)[1]), "r"((a)[2]), "r"((a)[3]), \
                   "r"(b0v), "r"(b1v))

// ============================================================================
// Prep 1 (fused): gate softmax + A' write (+ bias tail of A)
// ============================================================================
__global__ __launch_bounds__(256) void gate_splitx_kernel(
    const float* __restrict__ x, const float* __restrict__ Wg,
    const float* __restrict__ bg) {
    __shared__ float wgs[INF * NE];   // 32KB
    __shared__ float gs[8][NE];
    int tid = threadIdx.x;
    for (int i = tid; i < INF * NE / 4; i += 256)
        ((float4*)wgs)[i] = ((const float4*)Wg)[i];
    __syncthreads();

    int w = tid >> 5, lane = tid & 31;
    int t = blockIdx.x * 8 + w;
    const float* xr = x + (size_t)t * INF;

    float acc[NE];
#pragma unroll
    for (int e = 0; e < NE; e++) acc[e] = 0.f;
    for (int i = lane; i < INF; i += 32) {
        float xv = xr[i];
        float4 a = ((const float4*)wgs)[i * 2];
        float4 b = ((const float4*)wgs)[i * 2 + 1];
        acc[0] += xv * a.x; acc[1] += xv * a.y; acc[2] += xv * a.z; acc[3] += xv * a.w;
        acc[4] += xv * b.x; acc[5] += xv * b.y; acc[6] += xv * b.z; acc[7] += xv * b.w;
    }
#pragma unroll
    for (int e = 0; e < NE; e++)
#pragma unroll
        for (int off = 16; off; off >>= 1)
            acc[e] += __shfl_xor_sync(0xffffffffu, acc[e], off);

    if (lane == 0) {
        float mx = -1e30f;
#pragma unroll
        for (int e = 0; e < NE; e++) { acc[e] += bg[e]; mx = fmaxf(mx, acc[e]); }
        float s = 0.f;
#pragma unroll
        for (int e = 0; e < NE; e++) { acc[e] = expf(acc[e] - mx); s += acc[e]; }
        float inv = 1.0f / s;
#pragma unroll
        for (int e = 0; e < NE; e++) gs[w][e] = acc[e] * inv;
    }
    __syncthreads();

#pragma unroll 1
    for (int tok = 0; tok < 8; tok++) {
        int m = blockIdx.x * 8 + tok;
        const float* xs = x + (size_t)m * INF;
        __half* arow = g_A + (size_t)m * KTOT;
        for (int u = tid; u < 1024; u += 256) {
            int e  = u >> 7;
            int k8 = (u & 127) << 3;
            float g = gs[tok][e];
            float4 a = ((const float4*)(xs + k8))[0];
            float4 b = ((const float4*)(xs + k8))[1];
            float v[8] = {a.x, a.y, a.z, a.w, b.x, b.y, b.z, b.w};
            __align__(16) __half h[8];
#pragma unroll
            for (int i = 0; i < 8; i++) h[i] = __float2half_rn(g * v[i]);
            *(uint4*)(arow + e * INF + k8) = *(const uint4*)h;
        }
        for (int j = tid; j < 64; j += 256)
            arow[KSEG + j] = (j < NE) ? __float2half_rn(gs[tok][j]) : __half(0.f);
    }
}

// ============================================================================
// Prep 2: W'[n][e*1024+k] = fp16(We[e][k][n])  (smem transpose)
// ============================================================================
__global__ __launch_bounds__(256) void splitw_kernel(const float* __restrict__ We) {
    int b  = blockIdx.x;            // 8 * 32 * 32 = 8192 blocks
    int e  = b >> 10;
    int kt = (b >> 5) & 31;
    int nt = b & 31;

    __shared__ float tile[32][33];
    int tx = threadIdx.x & 31, ty = threadIdx.x >> 5;
    const float* base = We + (size_t)e * INF * OUTF;

#pragma unroll
    for (int i = 0; i < 4; i++) {
        int k = kt * 32 + ty + i * 8;
        tile[ty + i * 8][tx] = base[(size_t)k * OUTF + nt * 32 + tx];
    }
    __syncthreads();
#pragma unroll
    for (int i = 0; i < 4; i++) {
        int nrow = nt * 32 + ty + i * 8;
        float v = tile[tx][ty + i * 8];
        g_W[(size_t)nrow * KTOT + e * INF + kt * 32 + tx] = __float2half_rn(v);
    }
}

// Tail of W: W'[n][8192+j] = (j<8) ? be[j][n] : 0
__global__ __launch_bounds__(256) void tail_w_kernel(const float* __restrict__ be) {
    int idx = blockIdx.x * 256 + threadIdx.x;
    int n = idx >> 6;
    int j = idx & 63;
    g_W[(size_t)n * KTOT + KSEG + j] =
        (j < NE) ? __float2half_rn(be[(size_t)j * OUTF + n]) : __half(0.f);
}

// ============================================================================
// Main GEMM (split-K=2): split 0 -> out, split 1 -> g_P.
// CTA 128x128x64, 256 thr (8 warps 2m x 4n, warp tile 64x32), 3-stage
// cp.async, 2 CTAs per SM.
// ============================================================================
__device__ __forceinline__ void issue_stage(uint32_t stb, const char* gA,
                                            const char* gB, uint32_t sAo,
                                            int kbyte) {
#pragma unroll
    for (int v = 0; v < 4; v++)
        CP_ASYNC16(stb + sAo + v * 4096, gA + kbyte + (size_t)v * VSTRIDE32);
#pragma unroll
    for (int v = 0; v < 4; v++)
        CP_ASYNC16(stb + SB_B_OFF + sAo + v * 4096,
                   gB + kbyte + (size_t)v * VSTRIDE32);
    CP_COMMIT();
}

__global__ __launch_bounds__(THREADS, 2) void moe_gemm_kernel(
    float* __restrict__ out, float* __restrict__ part) {
    extern __shared__ __align__(128) char smem[];
    uint32_t sb = smem_u32(smem);

    int tid  = threadIdx.x;
    int lane = tid & 31;
    int wid  = tid >> 5;
    int wm   = wid & 1;          // 2 warp-rows  (m)  64 rows each
    int wn   = wid >> 1;         // 4 warp-cols  (n)  32 cols each
    int m0   = blockIdx.y * BM;
    int n0   = blockIdx.x * BN;
    int sp   = blockIdx.z;       // split id (0 or 1)
    int it0  = sp ? KSPLIT0 : 0;
    int nIt  = sp ? KSPLIT1 : KSPLIT0;

    // ---- cp.async per-thread invariants (256 thr: 32 rows x 8 chunks) ----
    int rA = tid >> 3;           // 0..31
    int ch = tid & 7;
    const char* gA = (const char*)(g_A + (size_t)(m0 + rA) * KTOT + ch * 8)
                     + (size_t)it0 * 128;
    const char* gB = (const char*)(g_W + (size_t)(n0 + rA) * KTOT + ch * 8)
                     + (size_t)it0 * 128;
    uint32_t sAo = (uint32_t)(rA * 128 + ((ch ^ (rA & 7)) << 4));

    // ---- ldmatrix per-thread invariants ----
    int aRow0 = wm * 64 + (lane & 15);
    int ah    = lane >> 4;
    int ax7   = aRow0 & 7;
    int bRow0 = wn * 32 + (lane & 7) + ((lane >> 4) << 3);
    int bh    = (lane >> 3) & 1;
    int bx7   = bRow0 & 7;

    uint32_t aBase[4], bBase[2];
#pragma unroll
    for (int mt = 0; mt < 4; mt++) aBase[mt] = (uint32_t)((aRow0 + mt * 16) * 128);
#pragma unroll
    for (int np = 0; np < 2; np++)
        bBase[np] = (uint32_t)(SB_B_OFF + (bRow0 + np * 16) * 128);

    float acc[4][4][4];
#pragma unroll
    for (int mt = 0; mt < 4; mt++)
#pragma unroll
        for (int nt = 0; nt < 4; nt++)
#pragma unroll
            for (int q = 0; q < 4; q++) acc[mt][nt][q] = 0.f;

    // ---- prologue: stages 0,1 (relative to it0) ----
    issue_stage(sb + 0 * STAGE_BYTES, gA, gB, sAo, 0 * 128);
    issue_stage(sb + 1 * STAGE_BYTES, gA, gB, sAo, 1 * 128);

    // ---- main loop ----
    int buf = 0;                      // relative stage i lives in buffer (i % 3)
    for (int i = 0; i < nIt; i++) {
        if (i < nIt - 1) CP_WAIT1(); else CP_WAIT0();
        __syncthreads();

        if (i + 2 < nIt) {
            int nb = buf + 2; if (nb >= STAGES) nb -= STAGES;
            issue_stage(sb + nb * STAGE_BYTES, gA, gB, sAo, (i + 2) * 128);
        }

        uint32_t stb = sb + buf * STAGE_BYTES;
        if (++buf == STAGES) buf = 0;

#pragma unroll
        for (int s = 0; s < 4; s++) {
            uint32_t cpA = (uint32_t)(((2 * s + ah) ^ ax7) << 4);
            uint32_t cpB = (uint32_t)(((2 * s + bh) ^ bx7) << 4);

            uint32_t af[4][4], bf[2][4];
#pragma unroll
            for (int mt = 0; mt < 4; mt++)
                LDSM_X4(af[mt][0], af[mt][1], af[mt][2], af[mt][3],
                        stb + aBase[mt] + cpA);
#pragma unroll
            for (int np = 0; np < 2; np++)
                LDSM_X4(bf[np][0], bf[np][1], bf[np][2], bf[np][3],
                        stb + bBase[np] + cpB);

#pragma unroll
            for (int mt = 0; mt < 4; mt++)
#pragma unroll
                for (int np = 0; np < 2; np++) {
                    MMA_16816(acc[mt][2 * np + 0], af[mt], bf[np][0], bf[np][1]);
                    MMA_16816(acc[mt][2 * np + 1], af[mt], bf[np][2], bf[np][3]);
                }
        }
    }

    // ---- epilogue: partial stores (split 0 -> out, split 1 -> g_P) ----
    float* dst = sp ? part : out;
    int grp = lane >> 2;
    int tig = lane & 3;
#pragma unroll
    for (int mt = 0; mt < 4; mt++) {
        int mrow = m0 + wm * 64 + mt * 16 + grp;
#pragma unroll
        for (int nt = 0; nt < 4; nt++) {
            int ncol = n0 + wn * 32 + nt * 8 + tig * 2;
            float2 v0 = make_float2(acc[mt][nt][0], acc[mt][nt][1]);
            float2 v1 = make_float2(acc[mt][nt][2], acc[mt][nt][3]);
            *(float2*)(dst + (size_t)mrow * OUTF + ncol)       = v0;
            *(float2*)(dst + (size_t)(mrow + 8) * OUTF + ncol) = v1;
        }
    }
}

// ============================================================================
// Reduce: out += g_P   (8192*1024 floats, float4 per thread)
// ============================================================================
__global__ __launch_bounds__(256) void reduce_kernel(float* __restrict__ out) {
    size_t i = ((size_t)blockIdx.x * 256 + threadIdx.x) * 4;
    float4 a = *(float4*)(out + i);
    float4 b = *(const float4*)(g_P + i);
    a.x += b.x; a.y += b.y; a.z += b.z; a.w += b.w;
    *(float4*)(out + i) = a;
}

// ============================================================================
// Launch
// ============================================================================
extern "C" void kernel_launch(void* const* d_in, const int* in_sizes, int n_in,
                              void* d_out, int out_size) {
    (void)in_sizes; (void)n_in; (void)out_size;
    const float* x  = (const float*)d_in[0];   // [8192, 1024]
    const float* We = (const float*)d_in[1];   // [8, 1024, 1024]
    const float* be = (const float*)d_in[2];   // [8, 1024]
    const float* Wg = (const float*)d_in[3];   // [1024, 8]
    const float* bg = (const float*)d_in[4];   // [8]
    float* out = (float*)d_out;                // [8192, 1024]

    float* part;
    cudaGetSymbolAddress((void**)&part, g_P);

    cudaFuncSetAttribute(moe_gemm_kernel,
                         cudaFuncAttributeMaxDynamicSharedMemorySize, SMEM_BYTES);

    gate_splitx_kernel<<<NTOK / 8, 256>>>(x, Wg, bg);
    splitw_kernel<<<NE * 32 * 32, 256>>>(We);
    tail_w_kernel<<<(OUTF * 64) / 256, 256>>>(be);
    moe_gemm_kernel<<<dim3(OUTF / BN, NTOK / BM, 2), THREADS, SMEM_BYTES>>>(out, part);
    reduce_kernel<<<(NTOK * OUTF) / (256 * 4), 256>>>(out);
}